// round 5
// baseline (speedup 1.0000x reference)
#include <cuda_runtime.h>

// ---------------------------------------------------------------------------
// Allegro GNN layer: streaming FFMA2 GEMMs (proven R4 core) with fused
// intermediates:
//   k12   : X0 -> (40->64 smem) -> (64->128) -> g_H      (H1 never hits HBM)
//   kvmix : P built in smem from wedge/env/Y -> @Wv0      (P never hits HBM)
//   kscal : scal0 only
// Rest identical to R4 (OpG3..G11 streaming GEMMs, kp2, red.global.v4).
// ---------------------------------------------------------------------------

#define NN 10000
#define NE 320000
#define NE3 960000
typedef unsigned long long ULL;

__device__ float g_X0  [NE * 40];
__device__ float g_H   [NE * 128];
__device__ float g_lat [NE * 128];
__device__ float g_wedge[NE * 64];
__device__ float g_scal0[NE * 64];
__device__ float g_smix[NE * 32];
__device__ float g_vmx [NE3 * 32];
__device__ float g_q   [NE * 64];
__device__ float g_Y   [NE * 4];
__device__ float g_fcut[NE];
__device__ float g_env [NN * 128];
__device__ float g_env1[NN * 128];

#define F_RS40      0.15811388300841897f
#define F_RS64      0.125f
#define F_RS96      0.10206207261596575f
#define F_RS128     0.08838834764831845f
#define F_RS192     0.07216878364870323f
#define F_ISN       0.17677669529663689f
#define F_SQRT3     1.7320508075688772f
#define F_INV_SQRT3 0.5773502691896258f
#define F_INV_SQRT2 0.7071067811865476f
#define F_C_OLD     0.8944271909999159f
#define F_C_NEW     0.4472135954999579f
#define F_BESSEL    0.6324555320336759f
#define F_PI        3.14159265358979323846f
#define F_INV_RMAX  0.2f

__device__ __forceinline__ ULL fma2(ULL a, ULL b, ULL c) {
    ULL d;
    asm("fma.rn.f32x2 %0, %1, %2, %3;" : "=l"(d) : "l"(a), "l"(b), "l"(c));
    return d;
}
__device__ __forceinline__ ULL pack2(float x) {
    ULL d; unsigned u = __float_as_uint(x);
    asm("mov.b64 %0, {%1,%1};" : "=l"(d) : "r"(u));
    return d;
}
__device__ __forceinline__ void red4(float* p, float a, float b, float c, float d) {
    asm volatile("red.global.add.v4.f32 [%0], {%1,%2,%3,%4};"
                 :: "l"(p), "f"(a), "f"(b), "f"(c), "f"(d) : "memory");
}
__device__ __forceinline__ float silu_f(float v) {
    return v * __frcp_rn(1.0f + __expf(-v));
}
__device__ __forceinline__ void cpa16(const void* s, const void* g) {
    unsigned sa = (unsigned)__cvta_generic_to_shared(s);
    asm volatile("cp.async.cg.shared.global [%0], [%1], 16;" :: "r"(sa), "l"(g));
}
__device__ __forceinline__ void cpa4(const void* s, const void* g) {
    unsigned sa = (unsigned)__cvta_generic_to_shared(s);
    asm volatile("cp.async.ca.shared.global [%0], [%1], 4;" :: "r"(sa), "l"(g));
}
__device__ __forceinline__ void cp_commit() { asm volatile("cp.async.commit_group;"); }
__device__ __forceinline__ void cp_wait1()  { asm volatile("cp.async.wait_group 1;"); }
__device__ __forceinline__ void cp_wait0()  { asm volatile("cp.async.wait_group 0;"); }

// ---------------------------------------------------------------------------
// Generic streaming GEMM (unchanged from R4).  BM=128 edge rows per tile.
// ---------------------------------------------------------------------------
template <int KTOT, int KC, int OUT, int OPO, class Op>
__global__ void __launch_bounds__(512, 1) gk(Op op, const float* __restrict__ Wg,
                                             int ntiles)
{
    constexpr int PC  = KC + 4;
    constexpr int NCH = KTOT / KC;
    constexpr int OG  = OUT / OPO;
    constexpr int OGW = OG / 4;
    constexpr int EGN = 512 / OG;
    constexpr int EPT = 128 / EGN;
    constexpr int NP  = OPO / 2;

    extern __shared__ __align__(16) float sh[];
    float* sW = sh;
    float* sX = sh + KTOT * OUT;

    int tid = threadIdx.x;
    for (int i = tid; i < KTOT * OUT / 4; i += 512)
        ((float4*)sW)[i] = ((const float4*)Wg)[i];

    int lane = tid & 31, w = tid >> 5;
    int og = (w & (OGW - 1)) * 4 + (lane & 3);
    int eg = (w / OGW) * 8 + (lane >> 2);

    auto stage = [&](long t, int c, int b) {
        float* dst = sX + b * (128 * PC);
        constexpr int UN = 128 * (KC / 4);
        for (int i = tid; i < UN; i += 512) {
            int e_l = i / (KC / 4);
            int ks  = (i % (KC / 4)) * 4;
            cpa16(dst + e_l * PC + ks, op.src(t * 128 + e_l, c * KC + ks));
        }
        cp_commit();
    };

    long t0 = blockIdx.x;
    if (t0 < ntiles) stage(t0, 0, 0);
    int b = 0;

    for (long t = t0; t < ntiles; t += gridDim.x) {
        ULL acc[EPT][NP];
#pragma unroll
        for (int j = 0; j < EPT; j++)
#pragma unroll
            for (int p = 0; p < NP; p++) acc[j][p] = 0ULL;

        for (int c = 0; c < NCH; c++) {
            long nt = t; int nc = c + 1;
            if (nc == NCH) { nt = t + gridDim.x; nc = 0; }
            bool hn = nt < ntiles;
            __syncthreads();
            if (hn) stage(nt, nc, b ^ 1);
            if (hn) cp_wait1(); else cp_wait0();
            __syncthreads();

            const float* Xb = sX + b * (128 * PC);
            const float* xr[EPT];
#pragma unroll
            for (int j = 0; j < EPT; j++) xr[j] = Xb + (eg + EGN * j) * PC;

#pragma unroll 2
            for (int k4 = 0; k4 < KC; k4 += 4) {
                float4 xv[EPT];
#pragma unroll
                for (int j = 0; j < EPT; j++)
                    xv[j] = *(const float4*)(xr[j] + k4);
#pragma unroll
                for (int kk = 0; kk < 4; kk++) {
                    const float* wr = sW + (c * KC + k4 + kk) * OUT + og * OPO;
                    ULL wv[NP];
#pragma unroll
                    for (int p = 0; p < NP; p++)
                        wv[p] = *(const ULL*)(wr + 2 * p);
#pragma unroll
                    for (int j = 0; j < EPT; j++) {
                        float xs = (kk == 0) ? xv[j].x : (kk == 1) ? xv[j].y
                                 : (kk == 2) ? xv[j].z : xv[j].w;
                        ULL xd = pack2(xs);
#pragma unroll
                        for (int p = 0; p < NP; p++)
                            acc[j][p] = fma2(xd, wv[p], acc[j][p]);
                    }
                }
            }
            b ^= 1;
        }

#pragma unroll
        for (int j = 0; j < EPT; j++) {
            long e = t * 128 + eg + EGN * j;
            float r[OPO];
#pragma unroll
            for (int p = 0; p < NP; p++) {
                union { ULL u; float2 f; } cv; cv.u = acc[j][p];
                r[2 * p] = cv.f.x; r[2 * p + 1] = cv.f.y;
            }
            op.epi(e, og, r);
        }
    }
}

// ---------------------------------------------------------------------------
// Epilogue / source policies
// ---------------------------------------------------------------------------
struct OpG3 {   // H(128) -> *fcut -> lat(128)
    __device__ const float* src(long e, int k) const { return g_H + e * 128 + k; }
    __device__ void epi(long e, int og, const float* r) const {
        float s = F_RS128 * g_fcut[e];
        *(float4*)(g_lat + e * 128 + og * 8) =
            make_float4(r[0] * s, r[1] * s, r[2] * s, r[3] * s);
        *(float4*)(g_lat + e * 128 + og * 8 + 4) =
            make_float4(r[4] * s, r[5] * s, r[6] * s, r[7] * s);
    }
};
struct OpG4 {   // lat -> w_all(128): outs 0-63 wedge, 64-127 env scatter
    const int* ctr;
    __device__ const float* src(long e, int k) const { return g_lat + e * 128 + k; }
    __device__ void epi(long e, int og, const float* r) const {
        if (og < 8) {
            *(float4*)(g_wedge + e * 64 + og * 8) =
                make_float4(r[0] * F_RS128, r[1] * F_RS128, r[2] * F_RS128, r[3] * F_RS128);
            *(float4*)(g_wedge + e * 64 + og * 8 + 4) =
                make_float4(r[4] * F_RS128, r[5] * F_RS128, r[6] * F_RS128, r[7] * F_RS128);
        } else {
            long c = ctr[e];
            float4 Y = *(const float4*)(g_Y + e * 4);
#pragma unroll
            for (int p = 0; p < 4; p++) {
                int m = (og - 8) * 4 + p;
                float w0 = r[2 * p] * F_RS128, w1 = r[2 * p + 1] * F_RS128;
                red4(g_env + c * 128 + 4 * m, w0, w1 * Y.y, w1 * Y.z, w1 * Y.w);
            }
        }
    }
};
struct OpG5 {   // scal0(64) -> smix(32)
    __device__ const float* src(long e, int k) const { return g_scal0 + e * 64 + k; }
    __device__ void epi(long e, int og, const float* r) const {
        *(float4*)(g_smix + e * 32 + og * 4) =
            make_float4(r[0] * F_RS64, r[1] * F_RS64, r[2] * F_RS64, r[3] * F_RS64);
    }
};
struct OpG7 {   // [lat|scal0](192) -> silu -> H(128)
    __device__ const float* src(long e, int k) const {
        return (k < 128) ? (g_lat + e * 128 + k) : (g_scal0 + e * 64 + (k - 128));
    }
    __device__ void epi(long e, int og, const float* r) const {
        *(float4*)(g_H + e * 128 + og * 8) =
            make_float4(silu_f(r[0] * F_RS192), silu_f(r[1] * F_RS192),
                        silu_f(r[2] * F_RS192), silu_f(r[3] * F_RS192));
        *(float4*)(g_H + e * 128 + og * 8 + 4) =
            make_float4(silu_f(r[4] * F_RS192), silu_f(r[5] * F_RS192),
                        silu_f(r[6] * F_RS192), silu_f(r[7] * F_RS192));
    }
};
struct OpG8 {   // H(128) -> *fcut, residual -> lat
    __device__ const float* src(long e, int k) const { return g_H + e * 128 + k; }
    __device__ void epi(long e, int og, const float* r) const {
        float s = F_C_NEW * F_RS128 * g_fcut[e];
        float4 l0 = *(const float4*)(g_lat + e * 128 + og * 8);
        float4 l1 = *(const float4*)(g_lat + e * 128 + og * 8 + 4);
        *(float4*)(g_lat + e * 128 + og * 8) =
            make_float4(F_C_OLD * l0.x + s * r[0], F_C_OLD * l0.y + s * r[1],
                        F_C_OLD * l0.z + s * r[2], F_C_OLD * l0.w + s * r[3]);
        *(float4*)(g_lat + e * 128 + og * 8 + 4) =
            make_float4(F_C_OLD * l1.x + s * r[4], F_C_OLD * l1.y + s * r[5],
                        F_C_OLD * l1.z + s * r[6], F_C_OLD * l1.w + s * r[7]);
    }
};
struct OpG9 {   // lat -> w_env1(64) -> env1 scatter
    const int* ctr;
    __device__ const float* src(long e, int k) const { return g_lat + e * 128 + k; }
    __device__ void epi(long e, int og, const float* r) const {
        long c = ctr[e];
        float4 Y = *(const float4*)(g_Y + e * 4);
        int m0 = og * 2;
        float w0 = r[0] * F_RS128, w1 = r[1] * F_RS128;
        red4(g_env1 + c * 128 + 4 * m0, w0, w1 * Y.y, w1 * Y.z, w1 * Y.w);
        float w2 = r[2] * F_RS128, w3 = r[3] * F_RS128;
        red4(g_env1 + c * 128 + 4 * (m0 + 1), w2, w3 * Y.y, w3 * Y.z, w3 * Y.w);
    }
};
struct OpG10 {  // [lat|q](192) -> silu -> H(128)
    __device__ const float* src(long e, int k) const {
        return (k < 128) ? (g_lat + e * 128 + k) : (g_q + e * 64 + (k - 128));
    }
    __device__ void epi(long e, int og, const float* r) const {
        *(float4*)(g_H + e * 128 + og * 8) =
            make_float4(silu_f(r[0] * F_RS192), silu_f(r[1] * F_RS192),
                        silu_f(r[2] * F_RS192), silu_f(r[3] * F_RS192));
        *(float4*)(g_H + e * 128 + og * 8 + 4) =
            make_float4(silu_f(r[4] * F_RS192), silu_f(r[5] * F_RS192),
                        silu_f(r[6] * F_RS192), silu_f(r[7] * F_RS192));
    }
};
struct OpG11 {  // H(128) -> *fcut, residual, *isn -> node scatter
    const int* ctr;
    float* out;
    __device__ const float* src(long e, int k) const { return g_H + e * 128 + k; }
    __device__ void epi(long e, int og, const float* r) const {
        long c = ctr[e];
        float s = F_C_NEW * F_RS128 * g_fcut[e];
        float4 l0 = *(const float4*)(g_lat + e * 128 + og * 8);
        float4 l1 = *(const float4*)(g_lat + e * 128 + og * 8 + 4);
        red4(out + c * 128 + og * 8,
             (F_C_OLD * l0.x + s * r[0]) * F_ISN, (F_C_OLD * l0.y + s * r[1]) * F_ISN,
             (F_C_OLD * l0.z + s * r[2]) * F_ISN, (F_C_OLD * l0.w + s * r[3]) * F_ISN);
        red4(out + c * 128 + og * 8 + 4,
             (F_C_OLD * l1.x + s * r[4]) * F_ISN, (F_C_OLD * l1.y + s * r[5]) * F_ISN,
             (F_C_OLD * l1.z + s * r[6]) * F_ISN, (F_C_OLD * l1.w + s * r[7]) * F_ISN);
    }
};

// ---------------------------------------------------------------------------
// k12: fused X0(40) -> silu(64, smem) -> silu(128) -> g_H
// smem: W0 2560 | W1 8192 | X0 dbuf 2*128*44 | H1 128*68
// ---------------------------------------------------------------------------
__global__ void __launch_bounds__(512, 1) k12(
    const float* __restrict__ W0g, const float* __restrict__ W1g, int ntiles)
{
    extern __shared__ __align__(16) float sh[];
    float* sW0 = sh;                    // 2560
    float* sW1 = sW0 + 2560;            // 8192
    float* sX  = sW1 + 8192;            // 2*128*44 = 11264
    float* sH1 = sX + 11264;            // 128*68 = 8704

    int tid = threadIdx.x;
    for (int i = tid; i < 2560 / 4; i += 512) ((float4*)sW0)[i] = ((const float4*)W0g)[i];
    for (int i = tid; i < 8192 / 4; i += 512) ((float4*)sW1)[i] = ((const float4*)W1g)[i];

    int lane = tid & 31, w = tid >> 5;
    // both GEMMs: OGW=4 mapping
    int og = (w & 3) * 4 + (lane & 3);      // 0..15
    int eg = (w >> 2) * 8 + (lane >> 2);    // 0..31

    auto stage = [&](long t, int b) {
        float* dst = sX + b * (128 * 44);
        for (int i = tid; i < 1280; i += 512) {
            int e_l = i / 10, ks = (i % 10) * 4;
            cpa16(dst + e_l * 44 + ks, g_X0 + (t * 128 + e_l) * 40 + ks);
        }
        cp_commit();
    };

    long t0 = blockIdx.x;
    if (t0 < ntiles) stage(t0, 0);
    int b = 0;

    for (long t = t0; t < ntiles; t += gridDim.x) {
        long nt = t + gridDim.x;
        bool hn = nt < ntiles;
        __syncthreads();
        if (hn) stage(nt, b ^ 1);
        if (hn) cp_wait1(); else cp_wait0();
        __syncthreads();

        // GEMM1: K=40, OUT=64 (OPO=4)
        {
            const float* Xb = sX + b * (128 * 44);
            ULL acc[4][2];
#pragma unroll
            for (int j = 0; j < 4; j++) { acc[j][0] = 0ULL; acc[j][1] = 0ULL; }
            const float* xr[4];
#pragma unroll
            for (int j = 0; j < 4; j++) xr[j] = Xb + (eg + 32 * j) * 44;
#pragma unroll 2
            for (int k4 = 0; k4 < 40; k4 += 4) {
                float4 xv[4];
#pragma unroll
                for (int j = 0; j < 4; j++) xv[j] = *(const float4*)(xr[j] + k4);
#pragma unroll
                for (int kk = 0; kk < 4; kk++) {
                    const float* wr = sW0 + (k4 + kk) * 64 + og * 4;
                    ULL w0 = *(const ULL*)wr, w1 = *(const ULL*)(wr + 2);
#pragma unroll
                    for (int j = 0; j < 4; j++) {
                        float xs = (kk == 0) ? xv[j].x : (kk == 1) ? xv[j].y
                                 : (kk == 2) ? xv[j].z : xv[j].w;
                        ULL xd = pack2(xs);
                        acc[j][0] = fma2(xd, w0, acc[j][0]);
                        acc[j][1] = fma2(xd, w1, acc[j][1]);
                    }
                }
            }
#pragma unroll
            for (int j = 0; j < 4; j++) {
                union { ULL u; float2 f; } c0, c1;
                c0.u = acc[j][0]; c1.u = acc[j][1];
                *(float4*)(sH1 + (eg + 32 * j) * 68 + og * 4) =
                    make_float4(silu_f(c0.f.x * F_RS40), silu_f(c0.f.y * F_RS40),
                                silu_f(c1.f.x * F_RS40), silu_f(c1.f.y * F_RS40));
            }
        }
        __syncthreads();

        // GEMM2: K=64 from sH1, OUT=128 (OPO=8)
        {
            ULL acc[4][4];
#pragma unroll
            for (int j = 0; j < 4; j++)
#pragma unroll
                for (int p = 0; p < 4; p++) acc[j][p] = 0ULL;
            const float* xr[4];
#pragma unroll
            for (int j = 0; j < 4; j++) xr[j] = sH1 + (eg + 32 * j) * 68;
#pragma unroll 2
            for (int k4 = 0; k4 < 64; k4 += 4) {
                float4 xv[4];
#pragma unroll
                for (int j = 0; j < 4; j++) xv[j] = *(const float4*)(xr[j] + k4);
#pragma unroll
                for (int kk = 0; kk < 4; kk++) {
                    const float* wr = sW1 + (k4 + kk) * 128 + og * 8;
                    ulonglong2 wa = *(const ulonglong2*)wr;
                    ulonglong2 wb = *(const ulonglong2*)(wr + 4);
#pragma unroll
                    for (int j = 0; j < 4; j++) {
                        float xs = (kk == 0) ? xv[j].x : (kk == 1) ? xv[j].y
                                 : (kk == 2) ? xv[j].z : xv[j].w;
                        ULL xd = pack2(xs);
                        acc[j][0] = fma2(xd, wa.x, acc[j][0]);
                        acc[j][1] = fma2(xd, wa.y, acc[j][1]);
                        acc[j][2] = fma2(xd, wb.x, acc[j][2]);
                        acc[j][3] = fma2(xd, wb.y, acc[j][3]);
                    }
                }
            }
#pragma unroll
            for (int j = 0; j < 4; j++) {
                long e = t * 128 + eg + 32 * j;
                union { ULL u; float2 f; } c0, c1, c2, c3;
                c0.u = acc[j][0]; c1.u = acc[j][1]; c2.u = acc[j][2]; c3.u = acc[j][3];
                *(float4*)(g_H + e * 128 + og * 8) =
                    make_float4(silu_f(c0.f.x * F_RS64), silu_f(c0.f.y * F_RS64),
                                silu_f(c1.f.x * F_RS64), silu_f(c1.f.y * F_RS64));
                *(float4*)(g_H + e * 128 + og * 8 + 4) =
                    make_float4(silu_f(c2.f.x * F_RS64), silu_f(c2.f.y * F_RS64),
                                silu_f(c3.f.x * F_RS64), silu_f(c3.f.y * F_RS64));
            }
        }
        b ^= 1;
    }
}

// ---------------------------------------------------------------------------
// kvmix: build P tile [128 rows][96] in smem from wedge/env/Y, GEMM @Wv0.
// rows r = 3e + c over [0, 3E).  scratch (dbuf): we[44][72] | Y[44][4] | ctr[44]
// ---------------------------------------------------------------------------
#define VSCR 3392
__global__ void __launch_bounds__(512, 1) kvmix(
    const int* __restrict__ ctr, const float* __restrict__ Wv, int ntiles)
{
    extern __shared__ __align__(16) float sh[];
    float* sW = sh;               // 96*32 = 3072
    float* sX = sW + 3072;        // 128*100 = 12800
    float* sS = sX + 12800;       // 2*VSCR

    int tid = threadIdx.x;
    for (int i = tid; i < 3072 / 4; i += 512) ((float4*)sW)[i] = ((const float4*)Wv)[i];

    int lane = tid & 31, w = tid >> 5;
    int og = (w & 1) * 4 + (lane & 3);       // 0..7
    int eg = (w >> 1) * 8 + (lane >> 2);     // 0..63

    auto stage = [&](long t, int b) {
        float* S = sS + b * VSCR;
        int e0e = (int)((t * 128) / 3);
        for (int i = tid; i < 704; i += 512) {          // we: 44 x 64
            int el = i >> 4, sub = i & 15;
            int e = e0e + el;
            if (e < NE) cpa16(S + el * 72 + sub * 4, g_wedge + (long)e * 64 + sub * 4);
        }
        for (int i = tid; i < 44; i += 512) {           // Y: 44 x 4
            int e = e0e + i;
            if (e < NE) cpa16(S + 3168 + i * 4, g_Y + (long)e * 4);
        }
        for (int i = tid; i < 44; i += 512) {           // ctr: 44 ints
            int e = e0e + i;
            if (e < NE) cpa4(S + 3344 + i, ctr + e);
        }
        cp_commit();
    };

    long t0 = blockIdx.x;
    if (t0 < ntiles) stage(t0, 0);
    int b = 0;

    int rl = tid >> 2;        // 0..127 local row
    int i0 = tid & 3;

    for (long t = t0; t < ntiles; t += gridDim.x) {
        cp_wait0();
        __syncthreads();
        float* S = sS + b * VSCR;
        int r0 = (int)(t * 128);
        int e0e = r0 / 3;

        // build P row rl
        {
            int gr = r0 + rl;
            int e  = gr / 3;
            int c  = gr - 3 * e;
            int el = e - e0e;
            const float* we = S + el * 72;
            float Y1 = S[3168 + el * 4 + 1];
            float Y2 = S[3168 + el * 4 + 2];
            float Y3 = S[3168 + el * 4 + 3];
            int ce = __float_as_int(S[3344 + el]);
            const float* envp = g_env + (long)ce * 128;
            float Yc = (c == 0) ? Y1 : (c == 1) ? Y2 : Y3;
            int aa = (c + 1) % 3, bb = (c + 2) % 3;
            float Ya = (aa == 0) ? Y1 : (aa == 1) ? Y2 : Y3;
            float Yb = (bb == 0) ? Y1 : (bb == 1) ? Y2 : Y3;
            float* Xr = sX + rl * 100;
#pragma unroll
            for (int q = 0; q < 8; q++) {               // block0: i = i0+4q
                int m = i0 + 4 * q;
                Xr[m] = we[2 * m] * envp[4 * m + 1 + c] * F_ISN;
            }
#pragma unroll
            for (int q = 0; q < 8; q++) {               // block1
                int m = i0 + 4 * q;
                Xr[32 + m] = we[2 * m + 1] * Yc * envp[4 * m] * F_ISN;
            }
#pragma unroll
            for (int q = 0; q < 8; q++) {               // block2 (cross)
                int m = i0 + 4 * q;
                Xr[64 + m] = we[2 * m + 1] *
                    (Ya * envp[4 * m + 1 + bb] - Yb * envp[4 * m + 1 + aa]) *
                    (F_ISN * F_INV_SQRT2);
            }
        }
        __syncthreads();

        long nt = t + gridDim.x;
        if (nt < ntiles) stage(nt, b ^ 1);

        // GEMM: [128][96] @ [96][32], EPT=2 (rows eg, eg+64)
        ULL a00 = 0, a01 = 0, a10 = 0, a11 = 0;
        const float* xr0 = sX + eg * 100;
        const float* xr1 = sX + (eg + 64) * 100;
#pragma unroll 2
        for (int k4 = 0; k4 < 96; k4 += 4) {
            float4 x0 = *(const float4*)(xr0 + k4);
            float4 x1 = *(const float4*)(xr1 + k4);
#pragma unroll
            for (int kk = 0; kk < 4; kk++) {
                const float* wr = sW + (k4 + kk) * 32 + og * 4;
                ULL w0 = *(const ULL*)wr, w1 = *(const ULL*)(wr + 2);
                float xs0 = (kk == 0) ? x0.x : (kk == 1) ? x0.y : (kk == 2) ? x0.z : x0.w;
                float xs1 = (kk == 0) ? x1.x : (kk == 1) ? x1.y : (kk == 2) ? x1.z : x1.w;
                ULL xd0 = pack2(xs0), xd1 = pack2(xs1);
                a00 = fma2(xd0, w0, a00); a01 = fma2(xd0, w1, a01);
                a10 = fma2(xd1, w0, a10); a11 = fma2(xd1, w1, a11);
            }
        }
        {
            union { ULL u; float2 f; } c0, c1;
            long rg = t * 128 + eg;
            c0.u = a00; c1.u = a01;
            *(float4*)(g_vmx + rg * 32 + og * 4) =
                make_float4(c0.f.x * F_RS96, c0.f.y * F_RS96,
                            c1.f.x * F_RS96, c1.f.y * F_RS96);
            c0.u = a10; c1.u = a11;
            *(float4*)(g_vmx + (rg + 64) * 32 + og * 4) =
                make_float4(c0.f.x * F_RS96, c0.f.y * F_RS96,
                            c1.f.x * F_RS96, c1.f.y * F_RS96);
        }
        b ^= 1;
    }
}

// ---------------------------------------------------------------------------
__global__ void k_zero(float* __restrict__ out)
{
    int i = blockIdx.x * blockDim.x + threadIdx.x;
    int stride = gridDim.x * blockDim.x;
    for (; i < NN * 128; i += stride) {
        g_env[i]  = 0.0f;
        g_env1[i] = 0.0f;
        out[i]    = 0.0f;
    }
}

__global__ void __launch_bounds__(256) kgeo(
    const float* __restrict__ coords, const float* __restrict__ attrs,
    const int* __restrict__ eidx)
{
    int e = blockIdx.x * 256 + threadIdx.x;
    if (e >= NE) return;
    int snd = eidx[e];
    int c   = eidx[NE + e];
    float dx = coords[c * 3 + 0] - coords[snd * 3 + 0];
    float dy = coords[c * 3 + 1] - coords[snd * 3 + 1];
    float dz = coords[c * 3 + 2] - coords[snd * 3 + 2];
    float r2 = dx * dx + dy * dy + dz * dz + 1e-12f;
    float r  = sqrtf(r2);
    float inv_r = 1.0f / r;
    float u  = r * F_INV_RMAX;
    float u2 = u * u, u3 = u2 * u, u6 = u3 * u3, u7 = u6 * u, u8 = u7 * u;
    float f  = 1.0f - 28.0f * u6 + 48.0f * u7 - 21.0f * u8;
    if (u >= 1.0f) f = 0.0f;
    g_fcut[e] = f;
    *(float4*)(g_Y + e * 4) = make_float4(1.0f, F_SQRT3 * dx * inv_r,
                                          F_SQRT3 * dy * inv_r, F_SQRT3 * dz * inv_r);
    float* X = g_X0 + (long)e * 40;
    const float4* ac = (const float4*)(attrs + c * 16);
    const float4* as = (const float4*)(attrs + snd * 16);
#pragma unroll
    for (int i = 0; i < 4; i++) ((float4*)X)[i] = ac[i];
#pragma unroll
    for (int i = 0; i < 4; i++) ((float4*)(X + 16))[i] = as[i];
    float bi = inv_r * f * F_BESSEL;
#pragma unroll
    for (int n = 0; n < 8; n++)
        X[32 + n] = bi * sinf((n + 1) * F_PI * u);
}

// kscal: scal0 only (thread per (e,m))
__global__ void __launch_bounds__(256) kscal(const int* __restrict__ ctr)
{
    long idx = (long)blockIdx.x * 256 + threadIdx.x;
    long stride = (long)gridDim.x * 256;
    for (; idx < (long)NE * 32; idx += stride) {
        long e = idx >> 5;
        int  m = (int)(idx & 31);
        long c = ctr[e];
        float2 we = *(const float2*)(g_wedge + e * 64 + 2 * m);
        float4 en = *(const float4*)(g_env + c * 128 + 4 * m);
        float4 Y  = *(const float4*)(g_Y + e * 4);
        float fs  = we.x;
        float fv0 = we.y * Y.y, fv1 = we.y * Y.z, fv2 = we.y * Y.w;
        float es  = en.x * F_ISN;
        float ev0 = en.y * F_ISN, ev1 = en.z * F_ISN, ev2 = en.w * F_ISN;
        g_scal0[e * 64 + m]      = fs * es;
        g_scal0[e * 64 + 32 + m] = (fv0 * ev0 + fv1 * ev1 + fv2 * ev2) * F_INV_SQRT3;
    }
}

// kp2: q0/q1 (warp per edge, lane = m)
__global__ void __launch_bounds__(256) kp2(const int* __restrict__ eidx)
{
    int warp = (blockIdx.x * 256 + threadIdx.x) >> 5;
    int lane = threadIdx.x & 31;
    int nw = gridDim.x * 8;
    for (long e = warp; e < NE; e += nw) {
        long c = eidx[NE + e];
        float4 e1 = *(const float4*)(g_env1 + c * 128 + 4 * lane);
        float sm = g_smix[e * 32 + lane];
        float v0 = g_vmx[(3 * e + 0) * 32 + lane];
        float v1 = g_vmx[(3 * e + 1) * 32 + lane];
        float v2 = g_vmx[(3 * e + 2) * 32 + lane];
        g_q[e * 64 + lane] = sm * e1.x * F_ISN;
        g_q[e * 64 + 32 + lane] =
            (v0 * e1.y + v1 * e1.z + v2 * e1.w) * F_ISN * F_INV_SQRT3;
    }
}

// ---------------------------------------------------------------------------
extern "C" void kernel_launch(void* const* d_in, const int* in_sizes, int n_in,
                              void* d_out, int out_size)
{
    const float* coords = (const float*)d_in[0];
    const float* attrs  = (const float*)d_in[1];
    const int*   eidx   = (const int*)  d_in[2];
    const float* W2b0   = (const float*)d_in[3];
    const float* W2b1   = (const float*)d_in[4];
    const float* W2b2   = (const float*)d_in[5];
    const float* Wenv0  = (const float*)d_in[6];
    const float* Wlat0  = (const float*)d_in[7];
    const float* Wlat1  = (const float*)d_in[8];
    const float* Ws0    = (const float*)d_in[9];
    const float* Wv0    = (const float*)d_in[10];
    const float* Wenv1  = (const float*)d_in[11];
    const float* Wfin0  = (const float*)d_in[12];
    const float* Wfin1  = (const float*)d_in[13];
    float* out = (float*)d_out;
    const int* ctr = eidx + NE;

    const size_t sm_k12    = (2560 + 8192 + 11264 + 8704) * 4;      // 122880
    const size_t sm_kvmix  = (3072 + 12800 + 2 * VSCR) * 4;         //  90624
    const size_t sm128_128 = (128 * 128 + 2 * 128 * 68) * 4;        // 135168
    const size_t sm64_32   = (64 * 32  + 2 * 128 * 68) * 4;         //  77824
    const size_t sm192_128 = (192 * 128 + 2 * 128 * 100) * 4;       // 200704
    const size_t sm128_64  = (128 * 64 + 2 * 128 * 68) * 4;         // 102400

    cudaFuncSetAttribute(k12,   cudaFuncAttributeMaxDynamicSharedMemorySize, (int)sm_k12);
    cudaFuncSetAttribute(kvmix, cudaFuncAttributeMaxDynamicSharedMemorySize, (int)sm_kvmix);
    cudaFuncSetAttribute(gk<128, 64, 128, 8, OpG3>,  cudaFuncAttributeMaxDynamicSharedMemorySize, (int)sm128_128);
    cudaFuncSetAttribute(gk<128, 64, 128, 8, OpG4>,  cudaFuncAttributeMaxDynamicSharedMemorySize, (int)sm128_128);
    cudaFuncSetAttribute(gk<64, 64, 32, 4, OpG5>,    cudaFuncAttributeMaxDynamicSharedMemorySize, (int)sm64_32);
    cudaFuncSetAttribute(gk<192, 96, 128, 8, OpG7>,  cudaFuncAttributeMaxDynamicSharedMemorySize, (int)sm192_128);
    cudaFuncSetAttribute(gk<128, 64, 128, 8, OpG8>,  cudaFuncAttributeMaxDynamicSharedMemorySize, (int)sm128_128);
    cudaFuncSetAttribute(gk<128, 64, 64, 4, OpG9>,   cudaFuncAttributeMaxDynamicSharedMemorySize, (int)sm128_64);
    cudaFuncSetAttribute(gk<192, 96, 128, 8, OpG10>, cudaFuncAttributeMaxDynamicSharedMemorySize, (int)sm192_128);
    cudaFuncSetAttribute(gk<128, 64, 128, 8, OpG11>, cudaFuncAttributeMaxDynamicSharedMemorySize, (int)sm128_128);

    const int NT  = NE / 128;    // 2500
    const int NT3 = NE3 / 128;   // 7500

    k_zero<<<512, 256>>>(out);
    kgeo<<<(NE + 255) / 256, 256>>>(coords, attrs, eidx);

    k12<<<148, 512, sm_k12>>>(W2b0, W2b1, NT);
    gk<128, 64, 128, 8, OpG3><<<148, 512, sm128_128>>>(OpG3{}, W2b2, NT);
    gk<128, 64, 128, 8, OpG4><<<148, 512, sm128_128>>>(OpG4{ctr}, Wenv0, NT);
    kscal<<<1280, 256>>>(ctr);
    gk<64, 64, 32, 4, OpG5><<<148, 512, sm64_32>>>(OpG5{}, Ws0, NT);
    kvmix<<<148, 512, sm_kvmix>>>(ctr, Wv0, NT3);
    gk<192, 96, 128, 8, OpG7><<<148, 512, sm192_128>>>(OpG7{}, Wlat0, NT);
    gk<128, 64, 128, 8, OpG8><<<148, 512, sm128_128>>>(OpG8{}, Wlat1, NT);
    gk<128, 64, 64, 4, OpG9><<<148, 512, sm128_64>>>(OpG9{ctr}, Wenv1, NT);
    kp2<<<1184, 256>>>(eidx);
    gk<192, 96, 128, 8, OpG10><<<148, 512, sm192_128>>>(OpG10{}, Wfin0, NT);
    gk<128, 64, 128, 8, OpG11><<<148, 512, sm128_128>>>(OpG11{ctr, out}, Wfin1, NT);
}

// round 7
// speedup vs baseline: 1.0759x; 1.0759x over previous
#include <cuda_runtime.h>

// ---------------------------------------------------------------------------
// Allegro GNN layer: streaming FFMA2 GEMMs.
//   k123  : X0 -> 40->64->128->128*fcut -> g_lat  (hiddens in smem, H1/H2
//           share one union region with sync-separated read/overwrite)
//   OpG4  : lat @ Wenv0 -> wedge + env scatter     (KC=128)
//   kp1   : products -> scal0 + P
//   OpG5  : scal0 @ Ws0 -> smix
//   OpG6  : P @ Wv0 -> vmx
//   OpG7/8: lat-update MLP + residual              (G8 KC=128)
//   OpG9  : lat @ Wenv1 -> env1 scatter            (KC=128)
//   kp2   : q0/q1
//   OpG10/11: final MLP + residual -> node scatter (G11 KC=128)
// ---------------------------------------------------------------------------

#define NN 10000
#define NE 320000
#define NE3 960000
typedef unsigned long long ULL;

__device__ float g_X0  [NE * 40];
__device__ float g_H   [NE * 128];
__device__ float g_lat [NE * 128];
__device__ float g_wedge[NE * 64];
__device__ float g_scal0[NE * 64];
__device__ float g_P   [(long)NE3 * 96];
__device__ float g_smix[NE * 32];
__device__ float g_vmx [NE3 * 32];
__device__ float g_q   [NE * 64];
__device__ float g_Y   [NE * 4];
__device__ float g_fcut[NE];
__device__ float g_env [NN * 128];
__device__ float g_env1[NN * 128];

#define F_RS40      0.15811388300841897f
#define F_RS64      0.125f
#define F_RS96      0.10206207261596575f
#define F_RS128     0.08838834764831845f
#define F_RS192     0.07216878364870323f
#define F_ISN       0.17677669529663689f
#define F_SQRT3     1.7320508075688772f
#define F_INV_SQRT3 0.5773502691896258f
#define F_INV_SQRT2 0.7071067811865476f
#define F_C_OLD     0.8944271909999159f
#define F_C_NEW     0.4472135954999579f
#define F_BESSEL    0.6324555320336759f
#define F_PI        3.14159265358979323846f
#define F_INV_RMAX  0.2f

__device__ __forceinline__ ULL fma2(ULL a, ULL b, ULL c) {
    ULL d;
    asm("fma.rn.f32x2 %0, %1, %2, %3;" : "=l"(d) : "l"(a), "l"(b), "l"(c));
    return d;
}
__device__ __forceinline__ ULL pack2(float x) {
    ULL d; unsigned u = __float_as_uint(x);
    asm("mov.b64 %0, {%1,%1};" : "=l"(d) : "r"(u));
    return d;
}
__device__ __forceinline__ void red4(float* p, float a, float b, float c, float d) {
    asm volatile("red.global.add.v4.f32 [%0], {%1,%2,%3,%4};"
                 :: "l"(p), "f"(a), "f"(b), "f"(c), "f"(d) : "memory");
}
__device__ __forceinline__ float silu_f(float v) {
    return v * __frcp_rn(1.0f + __expf(-v));
}
__device__ __forceinline__ void cpa16(const void* s, const void* g) {
    unsigned sa = (unsigned)__cvta_generic_to_shared(s);
    asm volatile("cp.async.cg.shared.global [%0], [%1], 16;" :: "r"(sa), "l"(g));
}
__device__ __forceinline__ void cp_commit() { asm volatile("cp.async.commit_group;"); }
__device__ __forceinline__ void cp_wait1()  { asm volatile("cp.async.wait_group 1;"); }
__device__ __forceinline__ void cp_wait0()  { asm volatile("cp.async.wait_group 0;"); }

// ---------------------------------------------------------------------------
// Generic streaming GEMM.  BM=128 edge rows per tile.
// ---------------------------------------------------------------------------
template <int KTOT, int KC, int OUT, int OPO, class Op>
__global__ void __launch_bounds__(512, 1) gk(Op op, const float* __restrict__ Wg,
                                             int ntiles)
{
    constexpr int PC  = KC + 4;
    constexpr int NCH = KTOT / KC;
    constexpr int OG  = OUT / OPO;
    constexpr int OGW = OG / 4;
    constexpr int EGN = 512 / OG;
    constexpr int EPT = 128 / EGN;
    constexpr int NP  = OPO / 2;

    extern __shared__ __align__(16) float sh[];
    float* sW = sh;
    float* sX = sh + KTOT * OUT;

    int tid = threadIdx.x;
    for (int i = tid; i < KTOT * OUT / 4; i += 512)
        ((float4*)sW)[i] = ((const float4*)Wg)[i];

    int lane = tid & 31, w = tid >> 5;
    int og = (w & (OGW - 1)) * 4 + (lane & 3);
    int eg = (w / OGW) * 8 + (lane >> 2);

    auto stage = [&](long t, int c, int b) {
        float* dst = sX + b * (128 * PC);
        constexpr int UN = 128 * (KC / 4);
        for (int i = tid; i < UN; i += 512) {
            int e_l = i / (KC / 4);
            int ks  = (i % (KC / 4)) * 4;
            cpa16(dst + e_l * PC + ks, op.src(t * 128 + e_l, c * KC + ks));
        }
        cp_commit();
    };

    long t0 = blockIdx.x;
    if (t0 < ntiles) stage(t0, 0, 0);
    int b = 0;

    for (long t = t0; t < ntiles; t += gridDim.x) {
        ULL acc[EPT][NP];
#pragma unroll
        for (int j = 0; j < EPT; j++)
#pragma unroll
            for (int p = 0; p < NP; p++) acc[j][p] = 0ULL;

        for (int c = 0; c < NCH; c++) {
            long nt = t; int nc = c + 1;
            if (nc == NCH) { nt = t + gridDim.x; nc = 0; }
            bool hn = nt < ntiles;
            __syncthreads();
            if (hn) stage(nt, nc, b ^ 1);
            if (hn) cp_wait1(); else cp_wait0();
            __syncthreads();

            const float* Xb = sX + b * (128 * PC);
            const float* xr[EPT];
#pragma unroll
            for (int j = 0; j < EPT; j++) xr[j] = Xb + (eg + EGN * j) * PC;

#pragma unroll 2
            for (int k4 = 0; k4 < KC; k4 += 4) {
                float4 xv[EPT];
#pragma unroll
                for (int j = 0; j < EPT; j++)
                    xv[j] = *(const float4*)(xr[j] + k4);
#pragma unroll
                for (int kk = 0; kk < 4; kk++) {
                    const float* wr = sW + (c * KC + k4 + kk) * OUT + og * OPO;
                    ULL wv[NP];
#pragma unroll
                    for (int p = 0; p < NP; p++)
                        wv[p] = *(const ULL*)(wr + 2 * p);
#pragma unroll
                    for (int j = 0; j < EPT; j++) {
                        float xs = (kk == 0) ? xv[j].x : (kk == 1) ? xv[j].y
                                 : (kk == 2) ? xv[j].z : xv[j].w;
                        ULL xd = pack2(xs);
#pragma unroll
                        for (int p = 0; p < NP; p++)
                            acc[j][p] = fma2(xd, wv[p], acc[j][p]);
                    }
                }
            }
            b ^= 1;
        }

#pragma unroll
        for (int j = 0; j < EPT; j++) {
            long e = t * 128 + eg + EGN * j;
            float r[OPO];
#pragma unroll
            for (int p = 0; p < NP; p++) {
                union { ULL u; float2 f; } cv; cv.u = acc[j][p];
                r[2 * p] = cv.f.x; r[2 * p + 1] = cv.f.y;
            }
            op.epi(e, og, r);
        }
    }
}

// ---------------------------------------------------------------------------
// Epilogue / source policies
// ---------------------------------------------------------------------------
struct OpG4 {   // lat -> w_all(128): outs 0-63 wedge, 64-127 env scatter
    const int* ctr;
    __device__ const float* src(long e, int k) const { return g_lat + e * 128 + k; }
    __device__ void epi(long e, int og, const float* r) const {
        if (og < 8) {
            *(float4*)(g_wedge + e * 64 + og * 8) =
                make_float4(r[0] * F_RS128, r[1] * F_RS128, r[2] * F_RS128, r[3] * F_RS128);
            *(float4*)(g_wedge + e * 64 + og * 8 + 4) =
                make_float4(r[4] * F_RS128, r[5] * F_RS128, r[6] * F_RS128, r[7] * F_RS128);
        } else {
            long c = ctr[e];
            float4 Y = *(const float4*)(g_Y + e * 4);
#pragma unroll
            for (int p = 0; p < 4; p++) {
                int m = (og - 8) * 4 + p;
                float w0 = r[2 * p] * F_RS128, w1 = r[2 * p + 1] * F_RS128;
                red4(g_env + c * 128 + 4 * m, w0, w1 * Y.y, w1 * Y.z, w1 * Y.w);
            }
        }
    }
};
struct OpG5 {   // scal0(64) -> smix(32)
    __device__ const float* src(long e, int k) const { return g_scal0 + e * 64 + k; }
    __device__ void epi(long e, int og, const float* r) const {
        *(float4*)(g_smix + e * 32 + og * 4) =
            make_float4(r[0] * F_RS64, r[1] * F_RS64, r[2] * F_RS64, r[3] * F_RS64);
    }
};
struct OpG6 {   // P(3E,96) -> vmx(3E,32)
    __device__ const float* src(long e, int k) const { return g_P + e * 96 + k; }
    __device__ void epi(long e, int og, const float* r) const {
        *(float4*)(g_vmx + e * 32 + og * 4) =
            make_float4(r[0] * F_RS96, r[1] * F_RS96, r[2] * F_RS96, r[3] * F_RS96);
    }
};
struct OpG7 {   // [lat|scal0](192) -> silu -> H(128)
    __device__ const float* src(long e, int k) const {
        return (k < 128) ? (g_lat + e * 128 + k) : (g_scal0 + e * 64 + (k - 128));
    }
    __device__ void epi(long e, int og, const float* r) const {
        *(float4*)(g_H + e * 128 + og * 8) =
            make_float4(silu_f(r[0] * F_RS192), silu_f(r[1] * F_RS192),
                        silu_f(r[2] * F_RS192), silu_f(r[3] * F_RS192));
        *(float4*)(g_H + e * 128 + og * 8 + 4) =
            make_float4(silu_f(r[4] * F_RS192), silu_f(r[5] * F_RS192),
                        silu_f(r[6] * F_RS192), silu_f(r[7] * F_RS192));
    }
};
struct OpG8 {   // H(128) -> *fcut, residual -> lat
    __device__ const float* src(long e, int k) const { return g_H + e * 128 + k; }
    __device__ void epi(long e, int og, const float* r) const {
        float s = F_C_NEW * F_RS128 * g_fcut[e];
        float4 l0 = *(const float4*)(g_lat + e * 128 + og * 8);
        float4 l1 = *(const float4*)(g_lat + e * 128 + og * 8 + 4);
        *(float4*)(g_lat + e * 128 + og * 8) =
            make_float4(F_C_OLD * l0.x + s * r[0], F_C_OLD * l0.y + s * r[1],
                        F_C_OLD * l0.z + s * r[2], F_C_OLD * l0.w + s * r[3]);
        *(float4*)(g_lat + e * 128 + og * 8 + 4) =
            make_float4(F_C_OLD * l1.x + s * r[4], F_C_OLD * l1.y + s * r[5],
                        F_C_OLD * l1.z + s * r[6], F_C_OLD * l1.w + s * r[7]);
    }
};
struct OpG9 {   // lat -> w_env1(64) -> env1 scatter
    const int* ctr;
    __device__ const float* src(long e, int k) const { return g_lat + e * 128 + k; }
    __device__ void epi(long e, int og, const float* r) const {
        long c = ctr[e];
        float4 Y = *(const float4*)(g_Y + e * 4);
        int m0 = og * 2;
        float w0 = r[0] * F_RS128, w1 = r[1] * F_RS128;
        red4(g_env1 + c * 128 + 4 * m0, w0, w1 * Y.y, w1 * Y.z, w1 * Y.w);
        float w2 = r[2] * F_RS128, w3 = r[3] * F_RS128;
        red4(g_env1 + c * 128 + 4 * (m0 + 1), w2, w3 * Y.y, w3 * Y.z, w3 * Y.w);
    }
};
struct OpG10 {  // [lat|q](192) -> silu -> H(128)
    __device__ const float* src(long e, int k) const {
        return (k < 128) ? (g_lat + e * 128 + k) : (g_q + e * 64 + (k - 128));
    }
    __device__ void epi(long e, int og, const float* r) const {
        *(float4*)(g_H + e * 128 + og * 8) =
            make_float4(silu_f(r[0] * F_RS192), silu_f(r[1] * F_RS192),
                        silu_f(r[2] * F_RS192), silu_f(r[3] * F_RS192));
        *(float4*)(g_H + e * 128 + og * 8 + 4) =
            make_float4(silu_f(r[4] * F_RS192), silu_f(r[5] * F_RS192),
                        silu_f(r[6] * F_RS192), silu_f(r[7] * F_RS192));
    }
};
struct OpG11 {  // H(128) -> *fcut, residual, *isn -> node scatter
    const int* ctr;
    float* out;
    __device__ const float* src(long e, int k) const { return g_H + e * 128 + k; }
    __device__ void epi(long e, int og, const float* r) const {
        long c = ctr[e];
        float s = F_C_NEW * F_RS128 * g_fcut[e];
        float4 l0 = *(const float4*)(g_lat + e * 128 + og * 8);
        float4 l1 = *(const float4*)(g_lat + e * 128 + og * 8 + 4);
        red4(out + c * 128 + og * 8,
             (F_C_OLD * l0.x + s * r[0]) * F_ISN, (F_C_OLD * l0.y + s * r[1]) * F_ISN,
             (F_C_OLD * l0.z + s * r[2]) * F_ISN, (F_C_OLD * l0.w + s * r[3]) * F_ISN);
        red4(out + c * 128 + og * 8 + 4,
             (F_C_OLD * l1.x + s * r[4]) * F_ISN, (F_C_OLD * l1.y + s * r[5]) * F_ISN,
             (F_C_OLD * l1.z + s * r[6]) * F_ISN, (F_C_OLD * l1.w + s * r[7]) * F_ISN);
    }
};

// ---------------------------------------------------------------------------
// k123: fused X0(40) -> silu(64) -> silu(128) -> *fcut*rs128 -> g_lat
// smem: W0 2560 | W1 8192 | W2 16384 | X dbuf 2*128*44 | HU 16896 (union)
//   HU holds H1 (pitch 68, 8704 fl) then H2 (pitch 132, 16896 fl).
//   GEMM2 reads all of H1 into registers, __syncthreads, then overwrites the
//   union region with H2.  Total 55296 floats = 221184 B.
// ---------------------------------------------------------------------------
__global__ void __launch_bounds__(512, 1) k123(
    const float* __restrict__ W0g, const float* __restrict__ W1g,
    const float* __restrict__ W2g, int ntiles)
{
    extern __shared__ __align__(16) float sh[];
    float* sW0 = sh;                    // 2560
    float* sW1 = sh + 2560;             // 8192
    float* sW2 = sh + 10752;            // 16384
    float* sX  = sh + 27136;            // 2*5632
    float* sHU = sh + 38400;            // 16896 union

    int tid = threadIdx.x;
    for (int i = tid; i < 2560 / 4;  i += 512) ((float4*)sW0)[i] = ((const float4*)W0g)[i];
    for (int i = tid; i < 8192 / 4;  i += 512) ((float4*)sW1)[i] = ((const float4*)W1g)[i];
    for (int i = tid; i < 16384 / 4; i += 512) ((float4*)sW2)[i] = ((const float4*)W2g)[i];

    int lane = tid & 31, w = tid >> 5;
    int og = (w & 3) * 4 + (lane & 3);      // 0..15
    int eg = (w >> 2) * 8 + (lane >> 2);    // 0..31

    auto stage = [&](long t, int b) {
        float* dst = sX + b * 5632;
        for (int i = tid; i < 1280; i += 512) {
            int e_l = i / 10, ks = (i % 10) * 4;
            cpa16(dst + e_l * 44 + ks, g_X0 + (t * 128 + e_l) * 40 + ks);
        }
        cp_commit();
    };

    long t0 = blockIdx.x;
    if (t0 < ntiles) stage(t0, 0);
    int b = 0;

    for (long t = t0; t < ntiles; t += gridDim.x) {
        long nt = t + gridDim.x;
        bool hn = nt < ntiles;
        __syncthreads();                    // prior tile's GEMM3 reads done
        if (hn) stage(nt, b ^ 1);
        if (hn) cp_wait1(); else cp_wait0();
        __syncthreads();

        // GEMM1: K=40 -> 64 (OPO=4) -> H1 (pitch 68)
        {
            const float* Xb = sX + b * 5632;
            ULL acc[4][2];
#pragma unroll
            for (int j = 0; j < 4; j++) { acc[j][0] = 0ULL; acc[j][1] = 0ULL; }
            const float* xr[4];
#pragma unroll
            for (int j = 0; j < 4; j++) xr[j] = Xb + (eg + 32 * j) * 44;
#pragma unroll 2
            for (int k4 = 0; k4 < 40; k4 += 4) {
                float4 xv[4];
#pragma unroll
                for (int j = 0; j < 4; j++) xv[j] = *(const float4*)(xr[j] + k4);
#pragma unroll
                for (int kk = 0; kk < 4; kk++) {
                    const float* wr = sW0 + (k4 + kk) * 64 + og * 4;
                    ULL w0 = *(const ULL*)wr, w1 = *(const ULL*)(wr + 2);
#pragma unroll
                    for (int j = 0; j < 4; j++) {
                        float xs = (kk == 0) ? xv[j].x : (kk == 1) ? xv[j].y
                                 : (kk == 2) ? xv[j].z : xv[j].w;
                        ULL xd = pack2(xs);
                        acc[j][0] = fma2(xd, w0, acc[j][0]);
                        acc[j][1] = fma2(xd, w1, acc[j][1]);
                    }
                }
            }
#pragma unroll
            for (int j = 0; j < 4; j++) {
                union { ULL u; float2 f; } c0, c1;
                c0.u = acc[j][0]; c1.u = acc[j][1];
                *(float4*)(sHU + (eg + 32 * j) * 68 + og * 4) =
                    make_float4(silu_f(c0.f.x * F_RS40), silu_f(c0.f.y * F_RS40),
                                silu_f(c1.f.x * F_RS40), silu_f(c1.f.y * F_RS40));
            }
        }
        __syncthreads();

        // GEMM2: K=64 read H1 (pitch 68) -> regs; sync; store H2 (pitch 132)
        {
            ULL acc[4][4];
#pragma unroll
            for (int j = 0; j < 4; j++)
#pragma unroll
                for (int p = 0; p < 4; p++) acc[j][p] = 0ULL;
            const float* xr[4];
#pragma unroll
            for (int j = 0; j < 4; j++) xr[j] = sHU + (eg + 32 * j) * 68;
#pragma unroll 2
            for (int k4 = 0; k4 < 64; k4 += 4) {
                float4 xv[4];
#pragma unroll
                for (int j = 0; j < 4; j++) xv[j] = *(const float4*)(xr[j] + k4);
#pragma unroll
                for (int kk = 0; kk < 4; kk++) {
                    const float* wr = sW1 + (k4 + kk) * 128 + og * 8;
                    ulonglong2 wa = *(const ulonglong2*)wr;
                    ulonglong2 wb = *(const ulonglong2*)(wr + 4);
#pragma unroll
                    for (int j = 0; j < 4; j++) {
                        float xs = (kk == 0) ? xv[j].x : (kk == 1) ? xv[j].y
                                 : (kk == 2) ? xv[j].z : xv[j].w;
                        ULL xd = pack2(xs);
                        acc[j][0] = fma2(xd, wa.x, acc[j][0]);
                        acc[j][1] = fma2(xd, wa.y, acc[j][1]);
                        acc[j][2] = fma2(xd, wb.x, acc[j][2]);
                        acc[j][3] = fma2(xd, wb.y, acc[j][3]);
                    }
                }
            }
            __syncthreads();   // ALL H1 reads complete before H2 overwrites
#pragma unroll
            for (int j = 0; j < 4; j++) {
                float* hr = sHU + (eg + 32 * j) * 132 + og * 8;
                union { ULL u; float2 f; } c0, c1, c2, c3;
                c0.u = acc[j][0]; c1.u = acc[j][1]; c2.u = acc[j][2]; c3.u = acc[j][3];
                *(float4*)hr =
                    make_float4(silu_f(c0.f.x * F_RS64), silu_f(c0.f.y * F_RS64),
                                silu_f(c1.f.x * F_RS64), silu_f(c1.f.y * F_RS64));
                *(float4*)(hr + 4) =
                    make_float4(silu_f(c2.f.x * F_RS64), silu_f(c2.f.y * F_RS64),
                                silu_f(c3.f.x * F_RS64), silu_f(c3.f.y * F_RS64));
            }
        }
        __syncthreads();

        // GEMM3: K=128 read H2 (pitch 132) -> *fcut -> g_lat
        {
            ULL acc[4][4];
#pragma unroll
            for (int j = 0; j < 4; j++)
#pragma unroll
                for (int p = 0; p < 4; p++) acc[j][p] = 0ULL;
            const float* xr[4];
#pragma unroll
            for (int j = 0; j < 4; j++) xr[j] = sHU + (eg + 32 * j) * 132;
#pragma unroll 2
            for (int k4 = 0; k4 < 128; k4 += 4) {
                float4 xv[4];
#pragma unroll
                for (int j = 0; j < 4; j++) xv[j] = *(const float4*)(xr[j] + k4);
#pragma unroll
                for (int kk = 0; kk < 4; kk++) {
                    const float* wr = sW2 + (k4 + kk) * 128 + og * 8;
                    ulonglong2 wa = *(const ulonglong2*)wr;
                    ulonglong2 wb = *(const ulonglong2*)(wr + 4);
#pragma unroll
                    for (int j = 0; j < 4; j++) {
                        float xs = (kk == 0) ? xv[j].x : (kk == 1) ? xv[j].y
                                 : (kk == 2) ? xv[j].z : xv[j].w;
                        ULL xd = pack2(xs);
                        acc[j][0] = fma2(xd, wa.x, acc[j][0]);
                        acc[j][1] = fma2(xd, wa.y, acc[j][1]);
                        acc[j][2] = fma2(xd, wb.x, acc[j][2]);
                        acc[j][3] = fma2(xd, wb.y, acc[j][3]);
                    }
                }
            }
#pragma unroll
            for (int j = 0; j < 4; j++) {
                long e = t * 128 + eg + 32 * j;
                float s = F_RS128 * g_fcut[e];
                union { ULL u; float2 f; } c0, c1, c2, c3;
                c0.u = acc[j][0]; c1.u = acc[j][1]; c2.u = acc[j][2]; c3.u = acc[j][3];
                *(float4*)(g_lat + e * 128 + og * 8) =
                    make_float4(c0.f.x * s, c0.f.y * s, c1.f.x * s, c1.f.y * s);
                *(float4*)(g_lat + e * 128 + og * 8 + 4) =
                    make_float4(c2.f.x * s, c2.f.y * s, c3.f.x * s, c3.f.y * s);
            }
        }
        b ^= 1;
    }
}

// ---------------------------------------------------------------------------
__global__ void k_zero(float* __restrict__ out)
{
    int i = blockIdx.x * blockDim.x + threadIdx.x;
    int stride = gridDim.x * blockDim.x;
    for (; i < NN * 128; i += stride) {
        g_env[i]  = 0.0f;
        g_env1[i] = 0.0f;
        out[i]    = 0.0f;
    }
}

__global__ void __launch_bounds__(256) kgeo(
    const float* __restrict__ coords, const float* __restrict__ attrs,
    const int* __restrict__ eidx)
{
    int e = blockIdx.x * 256 + threadIdx.x;
    if (e >= NE) return;
    int snd = eidx[e];
    int c   = eidx[NE + e];
    float dx = coords[c * 3 + 0] - coords[snd * 3 + 0];
    float dy = coords[c * 3 + 1] - coords[snd * 3 + 1];
    float dz = coords[c * 3 + 2] - coords[snd * 3 + 2];
    float r2 = dx * dx + dy * dy + dz * dz + 1e-12f;
    float r  = sqrtf(r2);
    float inv_r = 1.0f / r;
    float u  = r * F_INV_RMAX;
    float u2 = u * u, u3 = u2 * u, u6 = u3 * u3, u7 = u6 * u, u8 = u7 * u;
    float f  = 1.0f - 28.0f * u6 + 48.0f * u7 - 21.0f * u8;
    if (u >= 1.0f) f = 0.0f;
    g_fcut[e] = f;
    *(float4*)(g_Y + e * 4) = make_float4(1.0f, F_SQRT3 * dx * inv_r,
                                          F_SQRT3 * dy * inv_r, F_SQRT3 * dz * inv_r);
    float* X = g_X0 + (long)e * 40;
    const float4* ac = (const float4*)(attrs + c * 16);
    const float4* as = (const float4*)(attrs + snd * 16);
#pragma unroll
    for (int i = 0; i < 4; i++) ((float4*)X)[i] = ac[i];
#pragma unroll
    for (int i = 0; i < 4; i++) ((float4*)(X + 16))[i] = as[i];
    float bi = inv_r * f * F_BESSEL;
#pragma unroll
    for (int n = 0; n < 8; n++)
        X[32 + n] = bi * sinf((n + 1) * F_PI * u);
}

// kp1: products -> scal0 + P rows (warp per edge, lane = m)
__global__ void __launch_bounds__(256) kp1(const int* __restrict__ eidx)
{
    int warp = (blockIdx.x * 256 + threadIdx.x) >> 5;
    int lane = threadIdx.x & 31;
    int nw = gridDim.x * 8;
    for (long e = warp; e < NE; e += nw) {
        long c = eidx[NE + e];
        float2 we = *(const float2*)(g_wedge + e * 64 + 2 * lane);
        float4 en = *(const float4*)(g_env + c * 128 + 4 * lane);
        float4 Y  = *(const float4*)(g_Y + e * 4);
        float fs  = we.x;
        float fv0 = we.y * Y.y, fv1 = we.y * Y.z, fv2 = we.y * Y.w;
        float es  = en.x * F_ISN;
        float ev0 = en.y * F_ISN, ev1 = en.z * F_ISN, ev2 = en.w * F_ISN;
        g_scal0[e * 64 + lane]      = fs * es;
        g_scal0[e * 64 + 32 + lane] = (fv0 * ev0 + fv1 * ev1 + fv2 * ev2) * F_INV_SQRT3;
        float* P0 = g_P + (3 * e + 0) * 96;
        float* P1 = g_P + (3 * e + 1) * 96;
        float* P2 = g_P + (3 * e + 2) * 96;
        P0[lane] = fs * ev0;  P1[lane] = fs * ev1;  P2[lane] = fs * ev2;
        P0[32 + lane] = fv0 * es; P1[32 + lane] = fv1 * es; P2[32 + lane] = fv2 * es;
        P0[64 + lane] = (fv1 * ev2 - fv2 * ev1) * F_INV_SQRT2;
        P1[64 + lane] = (fv2 * ev0 - fv0 * ev2) * F_INV_SQRT2;
        P2[64 + lane] = (fv0 * ev1 - fv1 * ev0) * F_INV_SQRT2;
    }
}

// kp2: q0/q1 (warp per edge, lane = m)
__global__ void __launch_bounds__(256) kp2(const int* __restrict__ eidx)
{
    int warp = (blockIdx.x * 256 + threadIdx.x) >> 5;
    int lane = threadIdx.x & 31;
    int nw = gridDim.x * 8;
    for (long e = warp; e < NE; e += nw) {
        long c = eidx[NE + e];
        float4 e1 = *(const float4*)(g_env1 + c * 128 + 4 * lane);
        float sm = g_smix[e * 32 + lane];
        float v0 = g_vmx[(3 * e + 0) * 32 + lane];
        float v1 = g_vmx[(3 * e + 1) * 32 + lane];
        float v2 = g_vmx[(3 * e + 2) * 32 + lane];
        g_q[e * 64 + lane] = sm * e1.x * F_ISN;
        g_q[e * 64 + 32 + lane] =
            (v0 * e1.y + v1 * e1.z + v2 * e1.w) * F_ISN * F_INV_SQRT3;
    }
}

// ---------------------------------------------------------------------------
extern "C" void kernel_launch(void* const* d_in, const int* in_sizes, int n_in,
                              void* d_out, int out_size)
{
    const float* coords = (const float*)d_in[0];
    const float* attrs  = (const float*)d_in[1];
    const int*   eidx   = (const int*)  d_in[2];
    const float* W2b0   = (const float*)d_in[3];
    const float* W2b1   = (const float*)d_in[4];
    const float* W2b2   = (const float*)d_in[5];
    const float* Wenv0  = (const float*)d_in[6];
    const float* Wlat0  = (const float*)d_in[7];
    const float* Wlat1  = (const float*)d_in[8];
    const float* Ws0    = (const float*)d_in[9];
    const float* Wv0    = (const float*)d_in[10];
    const float* Wenv1  = (const float*)d_in[11];
    const float* Wfin0  = (const float*)d_in[12];
    const float* Wfin1  = (const float*)d_in[13];
    float* out = (float*)d_out;
    const int* ctr = eidx + NE;

    const size_t sm_k123    = (2560 + 8192 + 16384 + 11264 + 16896) * 4;  // 221184
    const size_t sm128_128c = (16384 + 2 * 128 * 132) * 4;                // 200704
    const size_t sm128_64c  = (8192 + 2 * 128 * 132) * 4;                 // 167936
    const size_t sm64_32    = (2048 + 2 * 128 * 68) * 4;                  //  77824
    const size_t sm96_32    = (3072 + 2 * 128 * 100) * 4;                 // 114688
    const size_t sm192_128  = (24576 + 2 * 128 * 100) * 4;                // 200704

    cudaFuncSetAttribute(k123, cudaFuncAttributeMaxDynamicSharedMemorySize, (int)sm_k123);
    cudaFuncSetAttribute(gk<128, 128, 128, 8, OpG4>,  cudaFuncAttributeMaxDynamicSharedMemorySize, (int)sm128_128c);
    cudaFuncSetAttribute(gk<64, 64, 32, 4, OpG5>,     cudaFuncAttributeMaxDynamicSharedMemorySize, (int)sm64_32);
    cudaFuncSetAttribute(gk<96, 96, 32, 4, OpG6>,     cudaFuncAttributeMaxDynamicSharedMemorySize, (int)sm96_32);
    cudaFuncSetAttribute(gk<192, 96, 128, 8, OpG7>,   cudaFuncAttributeMaxDynamicSharedMemorySize, (int)sm192_128);
    cudaFuncSetAttribute(gk<128, 128, 128, 8, OpG8>,  cudaFuncAttributeMaxDynamicSharedMemorySize, (int)sm128_128c);
    cudaFuncSetAttribute(gk<128, 128, 64, 4, OpG9>,   cudaFuncAttributeMaxDynamicSharedMemorySize, (int)sm128_64c);
    cudaFuncSetAttribute(gk<192, 96, 128, 8, OpG10>,  cudaFuncAttributeMaxDynamicSharedMemorySize, (int)sm192_128);
    cudaFuncSetAttribute(gk<128, 128, 128, 8, OpG11>, cudaFuncAttributeMaxDynamicSharedMemorySize, (int)sm128_128c);

    const int NT  = NE / 128;    // 2500
    const int NT3 = NE3 / 128;   // 7500

    k_zero<<<512, 256>>>(out);
    kgeo<<<(NE + 255) / 256, 256>>>(coords, attrs, eidx);

    k123<<<148, 512, sm_k123>>>(W2b0, W2b1, W2b2, NT);
    gk<128, 128, 128, 8, OpG4><<<148, 512, sm128_128c>>>(OpG4{ctr}, Wenv0, NT);
    kp1<<<640, 256>>>(eidx);
    gk<64, 64, 32, 4, OpG5><<<148, 512, sm64_32>>>(OpG5{}, Ws0, NT);
    gk<96, 96, 32, 4, OpG6><<<148, 512, sm96_32>>>(OpG6{}, Wv0, NT3);
    gk<192, 96, 128, 8, OpG7><<<148, 512, sm192_128>>>(OpG7{}, Wlat0, NT);
    gk<128, 128, 128, 8, OpG8><<<148, 512, sm128_128c>>>(OpG8{}, Wlat1, NT);
    gk<128, 128, 64, 4, OpG9><<<148, 512, sm128_64c>>>(OpG9{ctr}, Wenv1, NT);
    kp2<<<1184, 256>>>(eidx);
    gk<192, 96, 128, 8, OpG10><<<148, 512, sm192_128>>>(OpG10{}, Wfin0, NT);
    gk<128, 128, 128, 8, OpG11><<<148, 512, sm128_128c>>>(OpG11{ctr, out}, Wfin1, NT);
}